// round 1
// baseline (speedup 1.0000x reference)
#include <cuda_runtime.h>
#include <cstdint>

#define B_ 2
#define H_ 96
#define W_ 96
#define C_ 96
#define N_ (H_ * W_)          // 9216
#define GROUPS_ 32
#define HPG_ (H_ / GROUPS_)   // 3
#define BM 64
#define BN 64
#define NT 256

// ---------------- scratch (device globals; no allocation allowed) ----------------
__device__ float g_hn[B_ * N_ * C_];
__device__ float g_q [B_ * N_ * C_];
__device__ float g_k [B_ * N_ * C_];
__device__ float g_v [B_ * N_ * C_];
__device__ float g_o [B_ * N_ * C_];

// ---------------- GroupNorm over dim 1 (H) ----------------
// One block per (b, g). Group = rows h in [3g, 3g+3): contiguous 27648 floats.
__global__ __launch_bounds__(NT) void gn_kernel(const float* __restrict__ x,
                                                const float* __restrict__ gamma,
                                                const float* __restrict__ beta) {
    int bg = blockIdx.x;
    int b = bg / GROUPS_, g = bg % GROUPS_;
    const int LEN = HPG_ * W_ * C_;        // 27648
    const int NV = LEN / 4;                // 6912 float4
    size_t base = ((size_t)b * H_ + (size_t)g * HPG_) * (W_ * C_);
    const float4* xv = (const float4*)(x + base);

    float s = 0.f, ss = 0.f;
    for (int i = threadIdx.x; i < NV; i += NT) {
        float4 t = xv[i];
        s  += t.x + t.y + t.z + t.w;
        ss += t.x * t.x + t.y * t.y + t.z * t.z + t.w * t.w;
    }
    #pragma unroll
    for (int o = 16; o; o >>= 1) {
        s  += __shfl_xor_sync(0xffffffffu, s,  o);
        ss += __shfl_xor_sync(0xffffffffu, ss, o);
    }
    __shared__ float red[20];
    int w = threadIdx.x >> 5, l = threadIdx.x & 31;
    if (l == 0) { red[w] = s; red[w + 8] = ss; }
    __syncthreads();
    if (threadIdx.x == 0) {
        float S = 0.f, SS = 0.f;
        #pragma unroll
        for (int i = 0; i < 8; i++) { S += red[i]; SS += red[i + 8]; }
        float mean = S / LEN;
        float var = SS / LEN - mean * mean;
        red[16] = mean;
        red[17] = rsqrtf(var + 1e-5f);
    }
    __syncthreads();
    float mean = red[16], rstd = red[17];
    float4* hv = (float4*)(g_hn + base);
    const int ROWV = W_ * C_ / 4;          // 2304 float4 per h row
    for (int i = threadIdx.x; i < NV; i += NT) {
        float4 t = xv[i];
        int h = g * HPG_ + i / ROWV;
        float ga = gamma[h] * rstd;
        float be = beta[h] - mean * ga;
        float4 r;
        r.x = t.x * ga + be; r.y = t.y * ga + be;
        r.z = t.z * ga + be; r.w = t.w * ga + be;
        hv[i] = r;
    }
}

// ---------------- QKV projection: out = hn @ W + b ----------------
// blockIdx.x: 64-row block (288); blockIdx.y: 0=q 1=k 2=v.
// smem: W full (96x96) + hn tile (64 x 100-padded)
__global__ __launch_bounds__(NT) void qkv_kernel(const float* __restrict__ Wq, const float* __restrict__ bq,
                                                 const float* __restrict__ Wk, const float* __restrict__ bk,
                                                 const float* __restrict__ Wv, const float* __restrict__ bv) {
    extern __shared__ float sm[];
    float* Ws = sm;                 // 9216
    float* hs = sm + C_ * C_;       // 64*100
    const float* Wsel; const float* bsel; float* outp;
    if (blockIdx.y == 0)      { Wsel = Wq; bsel = bq; outp = g_q; }
    else if (blockIdx.y == 1) { Wsel = Wk; bsel = bk; outp = g_k; }
    else                      { Wsel = Wv; bsel = bv; outp = g_v; }

    int tid = threadIdx.x;
    int row0 = blockIdx.x * 64;
    for (int i = tid; i < C_ * C_ / 4; i += NT)
        ((float4*)Ws)[i] = ((const float4*)Wsel)[i];
    for (int i = tid; i < 64 * C_ / 4; i += NT) {
        int r = i / 24, c4 = i % 24;
        *(float4*)(hs + r * 100 + c4 * 4) =
            *(const float4*)(g_hn + ((size_t)(row0 + r)) * C_ + c4 * 4);
    }
    __syncthreads();

    int m = tid >> 2;
    int j0 = (tid & 3) * 24;
    float acc[24];
    #pragma unroll
    for (int u = 0; u < 24; u++) acc[u] = bsel[j0 + u];
    #pragma unroll 4
    for (int c = 0; c < C_; c++) {
        float a = hs[m * 100 + c];
        const float* wr = Ws + c * C_ + j0;
        #pragma unroll
        for (int u = 0; u < 24; u += 4) {
            float4 wv4 = *(const float4*)(wr + u);
            acc[u + 0] += a * wv4.x; acc[u + 1] += a * wv4.y;
            acc[u + 2] += a * wv4.z; acc[u + 3] += a * wv4.w;
        }
    }
    float* orow = outp + ((size_t)(row0 + m)) * C_ + j0;
    #pragma unroll
    for (int u = 0; u < 24; u += 4)
        *(float4*)(orow + u) = make_float4(acc[u], acc[u + 1], acc[u + 2], acc[u + 3]);
}

// ---------------- Flash attention, fp32 SIMT ----------------
// grid (144, 2); 256 threads; BM=BN=64, D=96.
// qT/kT: transposed [c][64] with XOR swizzle at float4 granularity for
// conflict-free LDS.128 in the S phase. vs natural [64][96]. ps [64][65].
__global__ __launch_bounds__(NT, 2) void attn_kernel() {
    extern __shared__ float sm[];
    float* qT      = sm;                  // 96*64
    float* kT      = qT + C_ * BM;        // 96*64
    float* vs      = kT + C_ * BN;        // 64*96
    float* ps      = vs + BN * C_;        // 64*65
    float* alpha_s = ps + BM * 65;        // 64
    float* l_s     = alpha_s + BM;        // 64

    int b   = blockIdx.y;
    int qb  = blockIdx.x;
    int tid = threadIdx.x;
    int tx = tid & 15, ty = tid >> 4;     // S-phase: 16x16 threads, 4x4 tiles
    int om = tid & 63, cg = tid >> 6;     // O-phase: 64 m x 4 channel groups
    int c0 = cg * 24;
    const float scale = 0.1020620726159657f;  // 96^-0.5

    // Load+scale Q tile, transposed + swizzled.
    const float* qg = g_q + ((size_t)b * N_ + (size_t)qb * BM) * C_;
    for (int i = tid; i < BM * C_; i += NT) {
        int n = i / C_, c = i % C_;
        qT[c * 64 + ((((n >> 2) ^ ((c >> 2) & 15)) << 2) | (n & 3))] = qg[i] * scale;
    }

    float mrun[4], lrun[4], oacc[24];
    #pragma unroll
    for (int i = 0; i < 4; i++) { mrun[i] = -1e30f; lrun[i] = 0.f; }
    #pragma unroll
    for (int u = 0; u < 24; u++) oacc[u] = 0.f;

    const float* kbase = g_k + (size_t)b * N_ * C_;
    const float* vbase = g_v + (size_t)b * N_ * C_;

    for (int kt = 0; kt < N_ / BN; kt++) {
        __syncthreads();   // protect prev iter's ps/vs/alpha reads
        const float* kg = kbase + (size_t)kt * BN * C_;
        const float* vg = vbase + (size_t)kt * BN * C_;
        for (int i = tid; i < BN * C_; i += NT) {
            int n = i / C_, c = i % C_;
            kT[c * 64 + ((((n >> 2) ^ ((c >> 2) & 15)) << 2) | (n & 3))] = kg[i];
        }
        for (int i = tid; i < BN * C_ / 4; i += NT)
            ((float4*)vs)[i] = ((const float4*)vg)[i];
        __syncthreads();

        // S = Q K^T (4x4 per thread)
        float s[4][4];
        #pragma unroll
        for (int i = 0; i < 4; i++)
            #pragma unroll
            for (int j = 0; j < 4; j++) s[i][j] = 0.f;

        #pragma unroll 4
        for (int c = 0; c < C_; c++) {
            int sw = (c >> 2) & 15;
            float4 qv = *(float4*)(qT + c * 64 + ((ty ^ sw) << 2));
            float4 kv = *(float4*)(kT + c * 64 + ((tx ^ sw) << 2));
            float qa[4] = {qv.x, qv.y, qv.z, qv.w};
            float ka[4] = {kv.x, kv.y, kv.z, kv.w};
            #pragma unroll
            for (int i = 0; i < 4; i++)
                #pragma unroll
                for (int j = 0; j < 4; j++) s[i][j] += qa[i] * ka[j];
        }

        // online softmax per row (row group = 16 lanes sharing ty)
        #pragma unroll
        for (int i = 0; i < 4; i++) {
            float rm = fmaxf(fmaxf(s[i][0], s[i][1]), fmaxf(s[i][2], s[i][3]));
            #pragma unroll
            for (int o = 8; o; o >>= 1)
                rm = fmaxf(rm, __shfl_xor_sync(0xffffffffu, rm, o));
            float mnew = fmaxf(mrun[i], rm);
            float p[4], rs = 0.f;
            #pragma unroll
            for (int j = 0; j < 4; j++) { p[j] = __expf(s[i][j] - mnew); rs += p[j]; }
            #pragma unroll
            for (int o = 8; o; o >>= 1)
                rs += __shfl_xor_sync(0xffffffffu, rs, o);
            float al = __expf(mrun[i] - mnew);
            lrun[i] = lrun[i] * al + rs;
            mrun[i] = mnew;
            if (tx == 0) alpha_s[ty * 4 + i] = al;
            #pragma unroll
            for (int j = 0; j < 4; j++) ps[(ty * 4 + i) * 65 + tx * 4 + j] = p[j];
        }
        __syncthreads();

        // O update: thread owns (om, 24 channels starting c0)
        float al = alpha_s[om];
        #pragma unroll
        for (int u = 0; u < 24; u++) oacc[u] *= al;
        #pragma unroll 2
        for (int j = 0; j < BN; j++) {
            float pv = ps[om * 65 + j];
            const float* vr = vs + j * C_ + c0;
            #pragma unroll
            for (int u = 0; u < 24; u += 4) {
                float4 vv = *(const float4*)(vr + u);
                oacc[u + 0] += pv * vv.x; oacc[u + 1] += pv * vv.y;
                oacc[u + 2] += pv * vv.z; oacc[u + 3] += pv * vv.w;
            }
        }
    }

    __syncthreads();
    if (tx == 0) {
        #pragma unroll
        for (int i = 0; i < 4; i++) l_s[ty * 4 + i] = lrun[i];
    }
    __syncthreads();
    float inv = 1.0f / l_s[om];
    float* og = g_o + ((size_t)b * N_ + (size_t)qb * BM + om) * C_ + c0;
    #pragma unroll
    for (int u = 0; u < 24; u += 4)
        *(float4*)(og + u) = make_float4(oacc[u] * inv, oacc[u + 1] * inv,
                                         oacc[u + 2] * inv, oacc[u + 3] * inv);
}

// ---------------- final projection + residual ----------------
__global__ __launch_bounds__(NT) void proj_kernel(const float* __restrict__ x,
                                                  const float* __restrict__ Wp,
                                                  const float* __restrict__ bp,
                                                  float* __restrict__ out) {
    extern __shared__ float sm[];
    float* Ws = sm;             // 9216
    float* os = sm + C_ * C_;   // 64*100
    int tid = threadIdx.x;
    int row0 = blockIdx.x * 64;
    for (int i = tid; i < C_ * C_ / 4; i += NT)
        ((float4*)Ws)[i] = ((const float4*)Wp)[i];
    for (int i = tid; i < 64 * C_ / 4; i += NT) {
        int r = i / 24, c4 = i % 24;
        *(float4*)(os + r * 100 + c4 * 4) =
            *(const float4*)(g_o + ((size_t)(row0 + r)) * C_ + c4 * 4);
    }
    __syncthreads();

    int m = tid >> 2;
    int j0 = (tid & 3) * 24;
    float acc[24];
    #pragma unroll
    for (int u = 0; u < 24; u++) acc[u] = bp[j0 + u];
    #pragma unroll 4
    for (int c = 0; c < C_; c++) {
        float a = os[m * 100 + c];
        const float* wr = Ws + c * C_ + j0;
        #pragma unroll
        for (int u = 0; u < 24; u += 4) {
            float4 wv4 = *(const float4*)(wr + u);
            acc[u + 0] += a * wv4.x; acc[u + 1] += a * wv4.y;
            acc[u + 2] += a * wv4.z; acc[u + 3] += a * wv4.w;
        }
    }
    size_t off = ((size_t)(row0 + m)) * C_ + j0;
    const float* xr = x + off;
    float* outr = out + off;
    #pragma unroll
    for (int u = 0; u < 24; u += 4) {
        float4 xv = *(const float4*)(xr + u);
        *(float4*)(outr + u) = make_float4(acc[u] + xv.x, acc[u + 1] + xv.y,
                                           acc[u + 2] + xv.z, acc[u + 3] + xv.w);
    }
}

// ---------------- launch ----------------
extern "C" void kernel_launch(void* const* d_in, const int* in_sizes, int n_in,
                              void* d_out, int out_size) {
    const float* x     = (const float*)d_in[0];
    const float* gamma = (const float*)d_in[1];
    const float* beta  = (const float*)d_in[2];
    const float* Wq    = (const float*)d_in[3];
    const float* bq    = (const float*)d_in[4];
    const float* Wk    = (const float*)d_in[5];
    const float* bk    = (const float*)d_in[6];
    const float* Wv    = (const float*)d_in[7];
    const float* bv    = (const float*)d_in[8];
    const float* Wp    = (const float*)d_in[9];
    const float* bp    = (const float*)d_in[10];
    float* out = (float*)d_out;

    const int SMEM_GEMM = (C_ * C_ + 64 * 100) * 4;                       // 62464
    const int SMEM_ATTN = (C_ * BM + C_ * BN + BN * C_ + BM * 65 + 128) * 4; // 90880

    cudaFuncSetAttribute(qkv_kernel,  cudaFuncAttributeMaxDynamicSharedMemorySize, SMEM_GEMM);
    cudaFuncSetAttribute(proj_kernel, cudaFuncAttributeMaxDynamicSharedMemorySize, SMEM_GEMM);
    cudaFuncSetAttribute(attn_kernel, cudaFuncAttributeMaxDynamicSharedMemorySize, SMEM_ATTN);

    gn_kernel<<<B_ * GROUPS_, NT>>>(x, gamma, beta);
    qkv_kernel<<<dim3(B_ * N_ / 64, 3), NT, SMEM_GEMM>>>(Wq, bq, Wk, bk, Wv, bv);
    attn_kernel<<<dim3(N_ / BM, B_), NT, SMEM_ATTN>>>();
    proj_kernel<<<B_ * N_ / 64, NT, SMEM_GEMM>>>(x, Wp, bp, out);
}

// round 3
// speedup vs baseline: 3.6351x; 3.6351x over previous
#include <cuda_runtime.h>
#include <cstdint>

#define B_ 2
#define H_ 96
#define W_ 96
#define C_ 96
#define N_ (H_ * W_)          // 9216
#define GROUPS_ 32
#define HPG_ (H_ / GROUPS_)   // 3
#define NT 256
#define BM 128
#define BN 64
#define KT_ (N_ / BN)         // 144 key tiles

// ---------------- scratch (device globals) ----------------
__device__ float g_hn[B_ * N_ * C_];
__device__ float g_q [B_ * N_ * C_];
__device__ float g_k [B_ * N_ * C_];
__device__ float g_v [B_ * N_ * C_];
__device__ float g_o [B_ * N_ * C_];

// ---------------- helpers ----------------
__device__ __forceinline__ uint32_t smem_u32(const void* p) {
    uint32_t a;
    asm("{ .reg .u64 t; cvta.to.shared.u64 t, %1; cvt.u32.u64 %0, t; }" : "=r"(a) : "l"(p));
    return a;
}
__device__ __forceinline__ uint32_t f2tf(float x) {
    uint32_t r; asm("cvt.rna.tf32.f32 %0, %1;" : "=r"(r) : "f"(x)); return r;
}
__device__ __forceinline__ void mma_tf32(float* d, const uint32_t* a, uint32_t b0, uint32_t b1) {
    asm volatile("mma.sync.aligned.m16n8k8.row.col.f32.tf32.tf32.f32 "
        "{%0,%1,%2,%3}, {%4,%5,%6,%7}, {%8,%9}, {%0,%1,%2,%3};"
        : "+f"(d[0]), "+f"(d[1]), "+f"(d[2]), "+f"(d[3])
        : "r"(a[0]), "r"(a[1]), "r"(a[2]), "r"(a[3]), "r"(b0), "r"(b1));
}
#define CP_ASYNC16(d, s) asm volatile("cp.async.cg.shared.global [%0], [%1], 16;" :: "r"(d), "l"(s) : "memory")
#define CP_COMMIT()      asm volatile("cp.async.commit_group;" ::: "memory")
#define CP_WAIT1()       asm volatile("cp.async.wait_group 1;" ::: "memory")
#define CP_WAIT0()       asm volatile("cp.async.wait_group 0;" ::: "memory")

// smem float offsets for attn
#define K0F 0
#define K1F 6400
#define V0F 12800
#define V1F 19200
#define PPF 25600
#define ATTN_SMEM_BYTES ((25600 + 128 * 68) * 4)   // 137216

// ---------------- GroupNorm ----------------
__global__ __launch_bounds__(NT) void gn_kernel(const float* __restrict__ x,
                                                const float* __restrict__ gamma,
                                                const float* __restrict__ beta) {
    int bg = blockIdx.x;
    int b = bg / GROUPS_, g = bg % GROUPS_;
    const int LEN = HPG_ * W_ * C_;
    const int NV = LEN / 4;
    size_t base = ((size_t)b * H_ + (size_t)g * HPG_) * (W_ * C_);
    const float4* xv = (const float4*)(x + base);

    float s = 0.f, ss = 0.f;
    for (int i = threadIdx.x; i < NV; i += NT) {
        float4 t = xv[i];
        s  += t.x + t.y + t.z + t.w;
        ss += t.x * t.x + t.y * t.y + t.z * t.z + t.w * t.w;
    }
    #pragma unroll
    for (int o = 16; o; o >>= 1) {
        s  += __shfl_xor_sync(0xffffffffu, s,  o);
        ss += __shfl_xor_sync(0xffffffffu, ss, o);
    }
    __shared__ float red[20];
    int w = threadIdx.x >> 5, l = threadIdx.x & 31;
    if (l == 0) { red[w] = s; red[w + 8] = ss; }
    __syncthreads();
    if (threadIdx.x == 0) {
        float S = 0.f, SS = 0.f;
        #pragma unroll
        for (int i = 0; i < 8; i++) { S += red[i]; SS += red[i + 8]; }
        float mean = S / LEN;
        float var = SS / LEN - mean * mean;
        red[16] = mean;
        red[17] = rsqrtf(var + 1e-5f);
    }
    __syncthreads();
    float mean = red[16], rstd = red[17];
    float4* hv = (float4*)(g_hn + base);
    const int ROWV = W_ * C_ / 4;
    for (int i = threadIdx.x; i < NV; i += NT) {
        float4 t = xv[i];
        int h = g * HPG_ + i / ROWV;
        float ga = gamma[h] * rstd;
        float be = beta[h] - mean * ga;
        float4 r;
        r.x = t.x * ga + be; r.y = t.y * ga + be;
        r.z = t.z * ga + be; r.w = t.w * ga + be;
        hv[i] = r;
    }
}

// ---------------- QKV projection (K and V rounded to tf32) ----------------
__global__ __launch_bounds__(NT) void qkv_kernel(const float* __restrict__ Wq, const float* __restrict__ bq,
                                                 const float* __restrict__ Wk, const float* __restrict__ bk,
                                                 const float* __restrict__ Wv, const float* __restrict__ bv) {
    extern __shared__ float sm[];
    float* Ws = sm;
    float* hs = sm + C_ * C_;
    const float* Wsel; const float* bsel; float* outp;
    if (blockIdx.y == 0)      { Wsel = Wq; bsel = bq; outp = g_q; }
    else if (blockIdx.y == 1) { Wsel = Wk; bsel = bk; outp = g_k; }
    else                      { Wsel = Wv; bsel = bv; outp = g_v; }

    int tid = threadIdx.x;
    int row0 = blockIdx.x * 64;
    for (int i = tid; i < C_ * C_ / 4; i += NT)
        ((float4*)Ws)[i] = ((const float4*)Wsel)[i];
    for (int i = tid; i < 64 * C_ / 4; i += NT) {
        int r = i / 24, c4 = i % 24;
        *(float4*)(hs + r * 100 + c4 * 4) =
            *(const float4*)(g_hn + ((size_t)(row0 + r)) * C_ + c4 * 4);
    }
    __syncthreads();

    int m = tid >> 2;
    int j0 = (tid & 3) * 24;
    float acc[24];
    #pragma unroll
    for (int u = 0; u < 24; u++) acc[u] = bsel[j0 + u];
    #pragma unroll 4
    for (int c = 0; c < C_; c++) {
        float a = hs[m * 100 + c];
        const float* wr = Ws + c * C_ + j0;
        #pragma unroll
        for (int u = 0; u < 24; u += 4) {
            float4 wv4 = *(const float4*)(wr + u);
            acc[u + 0] += a * wv4.x; acc[u + 1] += a * wv4.y;
            acc[u + 2] += a * wv4.z; acc[u + 3] += a * wv4.w;
        }
    }
    if (blockIdx.y != 0) {   // K, V: pre-round to tf32 (rna) for mma operands
        #pragma unroll
        for (int u = 0; u < 24; u++) acc[u] = __uint_as_float(f2tf(acc[u]));
    }
    float* orow = outp + ((size_t)(row0 + m)) * C_ + j0;
    #pragma unroll
    for (int u = 0; u < 24; u += 4)
        *(float4*)(orow + u) = make_float4(acc[u], acc[u + 1], acc[u + 2], acc[u + 3]);
}

// ---------------- flash attention with mma.sync tf32 ----------------
// grid (72, 2), 256 threads (8 warps), warp w owns rows [w*16, w*16+16).
// K/V smem tiles [64][100] (pad-100: frag loads conflict-free), P [128][68].
__global__ __launch_bounds__(NT, 1) void attn_kernel() {
    extern __shared__ float smf[];
    uint32_t sb = smem_u32(smf);
    uint32_t* smu = (uint32_t*)smf;

    int tid = threadIdx.x;
    int w = tid >> 5, lane = tid & 31;
    int g = lane >> 2, tg = lane & 3;
    int b = blockIdx.y, qb = blockIdx.x;
    const float scale = 0.10206207261596575f;

    // ---- Q fragments in registers (held for whole kernel) ----
    int mrow = qb * BM + w * 16;
    const float* qg = g_q + ((size_t)b * N_ + mrow) * C_;
    uint32_t qf[12][4];
    #pragma unroll
    for (int ks = 0; ks < 12; ks++) {
        qf[ks][0] = f2tf(qg[(size_t)g       * C_ + ks * 8 + tg]     * scale);
        qf[ks][1] = f2tf(qg[(size_t)(g + 8) * C_ + ks * 8 + tg]     * scale);
        qf[ks][2] = f2tf(qg[(size_t)g       * C_ + ks * 8 + tg + 4] * scale);
        qf[ks][3] = f2tf(qg[(size_t)(g + 8) * C_ + ks * 8 + tg + 4] * scale);
    }

    float o[12][4];
    #pragma unroll
    for (int nt = 0; nt < 12; nt++)
        #pragma unroll
        for (int j = 0; j < 4; j++) o[nt][j] = 0.f;
    float m0 = -3.0e38f, m1 = -3.0e38f, l0 = 0.f, l1 = 0.f;

    const float* kbase = g_k + (size_t)b * N_ * C_;
    const float* vbase = g_v + (size_t)b * N_ * C_;

    auto load_kv = [&](int kt, int buf) {
        const float* kg = kbase + (size_t)kt * BN * C_;
        const float* vg = vbase + (size_t)kt * BN * C_;
        uint32_t kb = sb + (buf ? K1F : K0F) * 4;
        uint32_t vb = sb + (buf ? V1F : V0F) * 4;
        #pragma unroll
        for (int i = 0; i < 6; i++) {
            int c = tid + i * NT;            // 0..1535
            int row = c / 24, q = c % 24;    // q = 16B chunk in row
            uint32_t so = (uint32_t)(row * 100 + q * 4) * 4;
            CP_ASYNC16(kb + so, kg + row * C_ + q * 4);
            CP_ASYNC16(vb + so, vg + row * C_ + q * 4);
        }
    };

    load_kv(0, 0);
    CP_COMMIT();

    int prow0 = (w * 16 + g) * 68;       // P row base (this thread, row g)
    int prow1 = (w * 16 + 8 + g) * 68;   // row g+8

    for (int t = 0; t < KT_; t++) {
        int buf = t & 1;
        const uint32_t* Ks = smu + (buf ? K1F : K0F);
        const uint32_t* Vs = smu + (buf ? V1F : V0F);
        uint32_t* Pp = smu + PPF;

        if (t + 1 < KT_) { load_kv(t + 1, buf ^ 1); CP_COMMIT(); CP_WAIT1(); }
        else             { CP_WAIT0(); }
        __syncthreads();

        // ---- S = Q K^T : 12 ksteps x 8 ntiles ----
        float s[8][4];
        #pragma unroll
        for (int nt = 0; nt < 8; nt++)
            #pragma unroll
            for (int j = 0; j < 4; j++) s[nt][j] = 0.f;

        #pragma unroll
        for (int ks = 0; ks < 12; ks++) {
            #pragma unroll
            for (int nt = 0; nt < 8; nt++) {
                uint32_t b0 = Ks[(nt * 8 + g) * 100 + ks * 8 + tg];
                uint32_t b1 = Ks[(nt * 8 + g) * 100 + ks * 8 + tg + 4];
                mma_tf32(s[nt], qf[ks], b0, b1);
            }
        }

        // ---- online softmax (rows g and g+8; reduce over 4 tg lanes) ----
        float rm0 = -3.0e38f, rm1 = -3.0e38f;
        #pragma unroll
        for (int nt = 0; nt < 8; nt++) {
            rm0 = fmaxf(rm0, fmaxf(s[nt][0], s[nt][1]));
            rm1 = fmaxf(rm1, fmaxf(s[nt][2], s[nt][3]));
        }
        rm0 = fmaxf(rm0, __shfl_xor_sync(0xffffffffu, rm0, 1));
        rm0 = fmaxf(rm0, __shfl_xor_sync(0xffffffffu, rm0, 2));
        rm1 = fmaxf(rm1, __shfl_xor_sync(0xffffffffu, rm1, 1));
        rm1 = fmaxf(rm1, __shfl_xor_sync(0xffffffffu, rm1, 2));

        float mn0 = fmaxf(m0, rm0), mn1 = fmaxf(m1, rm1);
        float a0 = __expf(m0 - mn0), a1 = __expf(m1 - mn1);
        m0 = mn0; m1 = mn1;

        float sum0 = 0.f, sum1 = 0.f;
        #pragma unroll
        for (int nt = 0; nt < 8; nt++) {
            float p0 = __expf(s[nt][0] - mn0);
            float p1 = __expf(s[nt][1] - mn0);
            float p2 = __expf(s[nt][2] - mn1);
            float p3 = __expf(s[nt][3] - mn1);
            sum0 += p0 + p1; sum1 += p2 + p3;
            *(uint2*)(Pp + prow0 + nt * 8 + 2 * tg) = make_uint2(f2tf(p0), f2tf(p1));
            *(uint2*)(Pp + prow1 + nt * 8 + 2 * tg) = make_uint2(f2tf(p2), f2tf(p3));
        }
        sum0 += __shfl_xor_sync(0xffffffffu, sum0, 1);
        sum0 += __shfl_xor_sync(0xffffffffu, sum0, 2);
        sum1 += __shfl_xor_sync(0xffffffffu, sum1, 1);
        sum1 += __shfl_xor_sync(0xffffffffu, sum1, 2);
        l0 = l0 * a0 + sum0;
        l1 = l1 * a1 + sum1;

        // rescale O
        #pragma unroll
        for (int nt = 0; nt < 12; nt++) {
            o[nt][0] *= a0; o[nt][1] *= a0;
            o[nt][2] *= a1; o[nt][3] *= a1;
        }
        __syncwarp();

        // ---- O += P V : 8 ksteps x 12 ntiles ----
        #pragma unroll
        for (int ks = 0; ks < 8; ks++) {
            uint32_t pa[4];
            pa[0] = Pp[prow0 + ks * 8 + tg];
            pa[1] = Pp[prow1 + ks * 8 + tg];
            pa[2] = Pp[prow0 + ks * 8 + tg + 4];
            pa[3] = Pp[prow1 + ks * 8 + tg + 4];
            #pragma unroll
            for (int nt = 0; nt < 12; nt++) {
                uint32_t b0 = Vs[(ks * 8 + tg) * 100 + nt * 8 + g];
                uint32_t b1 = Vs[(ks * 8 + tg + 4) * 100 + nt * 8 + g];
                mma_tf32(o[nt], pa, b0, b1);
            }
        }
        __syncthreads();
    }

    // ---- epilogue ----
    float i0 = 1.0f / l0, i1 = 1.0f / l1;
    float* og = g_o + ((size_t)b * N_ + mrow) * C_;
    #pragma unroll
    for (int nt = 0; nt < 12; nt++) {
        *(float2*)(og + (size_t)g       * C_ + nt * 8 + 2 * tg) = make_float2(o[nt][0] * i0, o[nt][1] * i0);
        *(float2*)(og + (size_t)(g + 8) * C_ + nt * 8 + 2 * tg) = make_float2(o[nt][2] * i1, o[nt][3] * i1);
    }
}

// ---------------- final projection + residual ----------------
__global__ __launch_bounds__(NT) void proj_kernel(const float* __restrict__ x,
                                                  const float* __restrict__ Wp,
                                                  const float* __restrict__ bp,
                                                  float* __restrict__ out) {
    extern __shared__ float sm[];
    float* Ws = sm;
    float* os = sm + C_ * C_;
    int tid = threadIdx.x;
    int row0 = blockIdx.x * 64;
    for (int i = tid; i < C_ * C_ / 4; i += NT)
        ((float4*)Ws)[i] = ((const float4*)Wp)[i];
    for (int i = tid; i < 64 * C_ / 4; i += NT) {
        int r = i / 24, c4 = i % 24;
        *(float4*)(os + r * 100 + c4 * 4) =
            *(const float4*)(g_o + ((size_t)(row0 + r)) * C_ + c4 * 4);
    }
    __syncthreads();

    int m = tid >> 2;
    int j0 = (tid & 3) * 24;
    float acc[24];
    #pragma unroll
    for (int u = 0; u < 24; u++) acc[u] = bp[j0 + u];
    #pragma unroll 4
    for (int c = 0; c < C_; c++) {
        float a = os[m * 100 + c];
        const float* wr = Ws + c * C_ + j0;
        #pragma unroll
        for (int u = 0; u < 24; u += 4) {
            float4 wv4 = *(const float4*)(wr + u);
            acc[u + 0] += a * wv4.x; acc[u + 1] += a * wv4.y;
            acc[u + 2] += a * wv4.z; acc[u + 3] += a * wv4.w;
        }
    }
    size_t off = ((size_t)(row0 + m)) * C_ + j0;
    const float* xr = x + off;
    float* outr = out + off;
    #pragma unroll
    for (int u = 0; u < 24; u += 4) {
        float4 xv = *(const float4*)(xr + u);
        *(float4*)(outr + u) = make_float4(acc[u] + xv.x, acc[u + 1] + xv.y,
                                           acc[u + 2] + xv.z, acc[u + 3] + xv.w);
    }
}

// ---------------- launch ----------------
extern "C" void kernel_launch(void* const* d_in, const int* in_sizes, int n_in,
                              void* d_out, int out_size) {
    const float* x     = (const float*)d_in[0];
    const float* gamma = (const float*)d_in[1];
    const float* beta  = (const float*)d_in[2];
    const float* Wq    = (const float*)d_in[3];
    const float* bq    = (const float*)d_in[4];
    const float* Wk    = (const float*)d_in[5];
    const float* bk    = (const float*)d_in[6];
    const float* Wv    = (const float*)d_in[7];
    const float* bv    = (const float*)d_in[8];
    const float* Wp    = (const float*)d_in[9];
    const float* bp    = (const float*)d_in[10];
    float* out = (float*)d_out;

    const int SMEM_GEMM = (C_ * C_ + 64 * 100) * 4;

    cudaFuncSetAttribute(qkv_kernel,  cudaFuncAttributeMaxDynamicSharedMemorySize, SMEM_GEMM);
    cudaFuncSetAttribute(proj_kernel, cudaFuncAttributeMaxDynamicSharedMemorySize, SMEM_GEMM);
    cudaFuncSetAttribute(attn_kernel, cudaFuncAttributeMaxDynamicSharedMemorySize, ATTN_SMEM_BYTES);

    gn_kernel<<<B_ * GROUPS_, NT>>>(x, gamma, beta);
    qkv_kernel<<<dim3(B_ * N_ / 64, 3), NT, SMEM_GEMM>>>(Wq, bq, Wk, bk, Wv, bv);
    attn_kernel<<<dim3(N_ / BM, B_), NT, ATTN_SMEM_BYTES>>>();
    proj_kernel<<<B_ * N_ / 64, NT, SMEM_GEMM>>>(x, Wp, bp, out);
}

// round 4
// speedup vs baseline: 7.4958x; 2.0621x over previous
#include <cuda_runtime.h>
#include <cuda_fp16.h>
#include <cstdint>

#define B_ 2
#define H_ 96
#define W_ 96
#define C_ 96
#define N_ (H_ * W_)          // 9216
#define GROUPS_ 32
#define HPG_ (H_ / GROUPS_)   // 3
#define NT 256
#define BM 128
#define BN 64
#define KT_ (N_ / BN)         // 144 key tiles

// ---------------- scratch (device globals) ----------------
__device__ float  g_hn[B_ * N_ * C_];
__device__ __half g_qh[B_ * N_ * C_];   // pre-scaled by 96^-0.5 * log2(e)
__device__ __half g_kh[B_ * N_ * C_];
__device__ __half g_vh[B_ * N_ * C_];
__device__ float  g_o [B_ * N_ * C_];

// ---------------- helpers ----------------
__device__ __forceinline__ uint32_t smem_u32(const void* p) {
    uint32_t a;
    asm("{ .reg .u64 t; cvta.to.shared.u64 t, %1; cvt.u32.u64 %0, t; }" : "=r"(a) : "l"(p));
    return a;
}
__device__ __forceinline__ void mma_f16(float* d, const uint32_t* a, uint32_t b0, uint32_t b1) {
    asm volatile("mma.sync.aligned.m16n8k16.row.col.f32.f16.f16.f32 "
        "{%0,%1,%2,%3}, {%4,%5,%6,%7}, {%8,%9}, {%0,%1,%2,%3};"
        : "+f"(d[0]), "+f"(d[1]), "+f"(d[2]), "+f"(d[3])
        : "r"(a[0]), "r"(a[1]), "r"(a[2]), "r"(a[3]), "r"(b0), "r"(b1));
}
__device__ __forceinline__ void ldsm4(uint32_t& r0, uint32_t& r1, uint32_t& r2, uint32_t& r3, uint32_t a) {
    asm volatile("ldmatrix.sync.aligned.m8n8.x4.shared.b16 {%0,%1,%2,%3}, [%4];"
        : "=r"(r0), "=r"(r1), "=r"(r2), "=r"(r3) : "r"(a));
}
__device__ __forceinline__ void ldsm4t(uint32_t& r0, uint32_t& r1, uint32_t& r2, uint32_t& r3, uint32_t a) {
    asm volatile("ldmatrix.sync.aligned.m8n8.x4.trans.shared.b16 {%0,%1,%2,%3}, [%4];"
        : "=r"(r0), "=r"(r1), "=r"(r2), "=r"(r3) : "r"(a));
}
__device__ __forceinline__ uint32_t h2pack(float lo, float hi) {
    __half2 h = __floats2half2_rn(lo, hi);
    return *(uint32_t*)&h;
}
#define CP_ASYNC16(d, s) asm volatile("cp.async.cg.shared.global [%0], [%1], 16;" :: "r"(d), "l"(s) : "memory")
#define CP_COMMIT()      asm volatile("cp.async.commit_group;" ::: "memory")
#define CP_WAIT0()       asm volatile("cp.async.wait_group 0;" ::: "memory")

// attn smem byte offsets: rows padded to 104 halves (208B) for conflict-free ldmatrix
#define ROWB 208
#define KB0 0
#define KB1 (KB0 + BN * ROWB)
#define VB0 (KB1 + BN * ROWB)
#define VB1 (VB0 + BN * ROWB)
#define ATTN_SMEM_BYTES (VB1 + BN * ROWB)   // 53248

// ---------------- GroupNorm ----------------
__global__ __launch_bounds__(NT) void gn_kernel(const float* __restrict__ x,
                                                const float* __restrict__ gamma,
                                                const float* __restrict__ beta) {
    int bg = blockIdx.x;
    int b = bg / GROUPS_, g = bg % GROUPS_;
    const int LEN = HPG_ * W_ * C_;
    const int NV = LEN / 4;
    size_t base = ((size_t)b * H_ + (size_t)g * HPG_) * (W_ * C_);
    const float4* xv = (const float4*)(x + base);

    float s = 0.f, ss = 0.f;
    for (int i = threadIdx.x; i < NV; i += NT) {
        float4 t = xv[i];
        s  += t.x + t.y + t.z + t.w;
        ss += t.x * t.x + t.y * t.y + t.z * t.z + t.w * t.w;
    }
    #pragma unroll
    for (int o = 16; o; o >>= 1) {
        s  += __shfl_xor_sync(0xffffffffu, s,  o);
        ss += __shfl_xor_sync(0xffffffffu, ss, o);
    }
    __shared__ float red[20];
    int w = threadIdx.x >> 5, l = threadIdx.x & 31;
    if (l == 0) { red[w] = s; red[w + 8] = ss; }
    __syncthreads();
    if (threadIdx.x == 0) {
        float S = 0.f, SS = 0.f;
        #pragma unroll
        for (int i = 0; i < 8; i++) { S += red[i]; SS += red[i + 8]; }
        float mean = S / LEN;
        float var = SS / LEN - mean * mean;
        red[16] = mean;
        red[17] = rsqrtf(var + 1e-5f);
    }
    __syncthreads();
    float mean = red[16], rstd = red[17];
    float4* hv = (float4*)(g_hn + base);
    const int ROWV = W_ * C_ / 4;
    for (int i = threadIdx.x; i < NV; i += NT) {
        float4 t = xv[i];
        int h = g * HPG_ + i / ROWV;
        float ga = gamma[h] * rstd;
        float be = beta[h] - mean * ga;
        float4 r;
        r.x = t.x * ga + be; r.y = t.y * ga + be;
        r.z = t.z * ga + be; r.w = t.w * ga + be;
        hv[i] = r;
    }
}

// ---------------- QKV projection -> fp16 (Q pre-scaled by scale*log2e) ----------------
__global__ __launch_bounds__(NT) void qkv_kernel(const float* __restrict__ Wq, const float* __restrict__ bq,
                                                 const float* __restrict__ Wk, const float* __restrict__ bk,
                                                 const float* __restrict__ Wv, const float* __restrict__ bv) {
    extern __shared__ float sm[];
    float* Ws = sm;
    float* hs = sm + C_ * C_;
    const float* Wsel; const float* bsel; __half* outp;
    if (blockIdx.y == 0)      { Wsel = Wq; bsel = bq; outp = g_qh; }
    else if (blockIdx.y == 1) { Wsel = Wk; bsel = bk; outp = g_kh; }
    else                      { Wsel = Wv; bsel = bv; outp = g_vh; }

    int tid = threadIdx.x;
    int row0 = blockIdx.x * 64;
    for (int i = tid; i < C_ * C_ / 4; i += NT)
        ((float4*)Ws)[i] = ((const float4*)Wsel)[i];
    for (int i = tid; i < 64 * C_ / 4; i += NT) {
        int r = i / 24, c4 = i % 24;
        *(float4*)(hs + r * 100 + c4 * 4) =
            *(const float4*)(g_hn + ((size_t)(row0 + r)) * C_ + c4 * 4);
    }
    __syncthreads();

    int m = tid >> 2;
    int j0 = (tid & 3) * 24;
    float acc[24];
    #pragma unroll
    for (int u = 0; u < 24; u++) acc[u] = bsel[j0 + u];
    #pragma unroll 4
    for (int c = 0; c < C_; c++) {
        float a = hs[m * 100 + c];
        const float* wr = Ws + c * C_ + j0;
        #pragma unroll
        for (int u = 0; u < 24; u += 4) {
            float4 wv4 = *(const float4*)(wr + u);
            acc[u + 0] += a * wv4.x; acc[u + 1] += a * wv4.y;
            acc[u + 2] += a * wv4.z; acc[u + 3] += a * wv4.w;
        }
    }
    // Q: bake softmax scale and log2(e) so attention uses exp2
    if (blockIdx.y == 0) {
        const float qs = 0.10206207261596575f * 1.4426950408889634f;
        #pragma unroll
        for (int u = 0; u < 24; u++) acc[u] *= qs;
    }
    __half* orow = outp + ((size_t)(row0 + m)) * C_ + j0;
    #pragma unroll
    for (int u = 0; u < 24; u += 2)
        *(__half2*)(orow + u) = __floats2half2_rn(acc[u], acc[u + 1]);
}

// ---------------- flash attention, fp16 mma.sync m16n8k16 ----------------
// grid (72, 2), 256 threads (8 warps), warp w owns rows [16w, 16w+16).
// K/V smem: [64][104 halves]; Q frags + P frags + O accum in registers.
__global__ __launch_bounds__(NT, 1) void attn_kernel() {
    extern __shared__ __half smh[];
    uint32_t sb = smem_u32(smh);

    int tid = threadIdx.x;
    int w = tid >> 5, l = tid & 31;
    int g = l >> 2, tg = l & 3;
    int b = blockIdx.y, qb = blockIdx.x;

    // ---- Q fragments in registers ----
    int mrow = qb * BM + w * 16;
    const __half* qg = g_qh + ((size_t)b * N_ + mrow) * C_;
    uint32_t qf[6][4];
    #pragma unroll
    for (int ks = 0; ks < 6; ks++) {
        qf[ks][0] = *(const uint32_t*)(qg + (size_t)g       * C_ + ks * 16 + 2 * tg);
        qf[ks][1] = *(const uint32_t*)(qg + (size_t)(g + 8) * C_ + ks * 16 + 2 * tg);
        qf[ks][2] = *(const uint32_t*)(qg + (size_t)g       * C_ + ks * 16 + 2 * tg + 8);
        qf[ks][3] = *(const uint32_t*)(qg + (size_t)(g + 8) * C_ + ks * 16 + 2 * tg + 8);
    }

    float o[12][4];
    #pragma unroll
    for (int nt = 0; nt < 12; nt++)
        #pragma unroll
        for (int j = 0; j < 4; j++) o[nt][j] = 0.f;
    float m0 = -3.0e38f, m1 = -3.0e38f, l0 = 0.f, l1 = 0.f;

    // per-lane ldmatrix offsets (bytes)
    uint32_t klane = (uint32_t)(((l & 7) + 8 * ((l >> 4) & 1)) * ROWB + 8 * ((l >> 3) & 1) * 2);
    uint32_t vlane = (uint32_t)(((l & 7) + 8 * ((l >> 3) & 1)) * ROWB + 8 * (l >> 4) * 2);

    const __half* kbase = g_kh + (size_t)b * N_ * C_;
    const __half* vbase = g_vh + (size_t)b * N_ * C_;

    auto load_kv = [&](int kt, int buf) {
        const __half* kg = kbase + (size_t)kt * BN * C_;
        const __half* vg = vbase + (size_t)kt * BN * C_;
        uint32_t kb = sb + (buf ? KB1 : KB0);
        uint32_t vb = sb + (buf ? VB1 : VB0);
        #pragma unroll
        for (int i = 0; i < 3; i++) {
            int c = tid + i * NT;            // 0..767
            int row = c / 12, q = c % 12;    // q = 16B chunk in row
            uint32_t so = (uint32_t)(row * ROWB + q * 16);
            CP_ASYNC16(kb + so, kg + row * C_ + q * 8);
            CP_ASYNC16(vb + so, vg + row * C_ + q * 8);
        }
    };

    load_kv(0, 0);
    CP_COMMIT();

    for (int t = 0; t < KT_; t++) {
        int buf = t & 1;
        uint32_t Kb = sb + (buf ? KB1 : KB0);
        uint32_t Vb = sb + (buf ? VB1 : VB0);

        CP_WAIT0();
        __syncthreads();
        if (t + 1 < KT_) { load_kv(t + 1, buf ^ 1); CP_COMMIT(); }

        // ---- S = Q K^T : 6 ksteps x 4 n16-pairs ----
        float s[8][4];
        #pragma unroll
        for (int nt = 0; nt < 8; nt++)
            #pragma unroll
            for (int j = 0; j < 4; j++) s[nt][j] = 0.f;

        #pragma unroll
        for (int ks = 0; ks < 6; ks++) {
            #pragma unroll
            for (int np = 0; np < 4; np++) {
                uint32_t b0, b1, b2, b3;
                ldsm4(b0, b1, b2, b3, Kb + (uint32_t)(np * 16 * ROWB + ks * 32) + klane);
                mma_f16(s[2 * np],     qf[ks], b0, b1);
                mma_f16(s[2 * np + 1], qf[ks], b2, b3);
            }
        }

        // ---- online softmax (rows g, g+8; reduce over tg lanes), exp2 domain ----
        float rm0 = -3.0e38f, rm1 = -3.0e38f;
        #pragma unroll
        for (int nt = 0; nt < 8; nt++) {
            rm0 = fmaxf(rm0, fmaxf(s[nt][0], s[nt][1]));
            rm1 = fmaxf(rm1, fmaxf(s[nt][2], s[nt][3]));
        }
        rm0 = fmaxf(rm0, __shfl_xor_sync(0xffffffffu, rm0, 1));
        rm0 = fmaxf(rm0, __shfl_xor_sync(0xffffffffu, rm0, 2));
        rm1 = fmaxf(rm1, __shfl_xor_sync(0xffffffffu, rm1, 1));
        rm1 = fmaxf(rm1, __shfl_xor_sync(0xffffffffu, rm1, 2));

        float mn0 = fmaxf(m0, rm0), mn1 = fmaxf(m1, rm1);
        float a0 = exp2f(m0 - mn0), a1 = exp2f(m1 - mn1);
        m0 = mn0; m1 = mn1;

        float sum0 = 0.f, sum1 = 0.f;
        #pragma unroll
        for (int nt = 0; nt < 8; nt++) {
            s[nt][0] = exp2f(s[nt][0] - mn0);
            s[nt][1] = exp2f(s[nt][1] - mn0);
            s[nt][2] = exp2f(s[nt][2] - mn1);
            s[nt][3] = exp2f(s[nt][3] - mn1);
            sum0 += s[nt][0] + s[nt][1];
            sum1 += s[nt][2] + s[nt][3];
        }
        sum0 += __shfl_xor_sync(0xffffffffu, sum0, 1);
        sum0 += __shfl_xor_sync(0xffffffffu, sum0, 2);
        sum1 += __shfl_xor_sync(0xffffffffu, sum1, 1);
        sum1 += __shfl_xor_sync(0xffffffffu, sum1, 2);
        l0 = l0 * a0 + sum0;
        l1 = l1 * a1 + sum1;

        // rescale O
        #pragma unroll
        for (int nt = 0; nt < 12; nt++) {
            o[nt][0] *= a0; o[nt][1] *= a0;
            o[nt][2] *= a1; o[nt][3] *= a1;
        }

        // ---- O += P V : P stays in registers as A-frags ----
        #pragma unroll
        for (int ks = 0; ks < 4; ks++) {
            uint32_t pa[4];
            pa[0] = h2pack(s[2 * ks][0],     s[2 * ks][1]);
            pa[1] = h2pack(s[2 * ks][2],     s[2 * ks][3]);
            pa[2] = h2pack(s[2 * ks + 1][0], s[2 * ks + 1][1]);
            pa[3] = h2pack(s[2 * ks + 1][2], s[2 * ks + 1][3]);
            #pragma unroll
            for (int np = 0; np < 6; np++) {
                uint32_t b0, b1, b2, b3;
                ldsm4t(b0, b1, b2, b3, Vb + (uint32_t)(ks * 16 * ROWB + np * 32) + vlane);
                mma_f16(o[2 * np],     pa, b0, b1);
                mma_f16(o[2 * np + 1], pa, b2, b3);
            }
        }
    }

    // ---- epilogue ----
    float i0 = 1.0f / l0, i1 = 1.0f / l1;
    float* og = g_o + ((size_t)b * N_ + mrow) * C_;
    #pragma unroll
    for (int nt = 0; nt < 12; nt++) {
        *(float2*)(og + (size_t)g       * C_ + nt * 8 + 2 * tg) = make_float2(o[nt][0] * i0, o[nt][1] * i0);
        *(float2*)(og + (size_t)(g + 8) * C_ + nt * 8 + 2 * tg) = make_float2(o[nt][2] * i1, o[nt][3] * i1);
    }
}

// ---------------- final projection + residual ----------------
__global__ __launch_bounds__(NT) void proj_kernel(const float* __restrict__ x,
                                                  const float* __restrict__ Wp,
                                                  const float* __restrict__ bp,
                                                  float* __restrict__ out) {
    extern __shared__ float sm[];
    float* Ws = sm;
    float* os = sm + C_ * C_;
    int tid = threadIdx.x;
    int row0 = blockIdx.x * 64;
    for (int i = tid; i < C_ * C_ / 4; i += NT)
        ((float4*)Ws)[i] = ((const float4*)Wp)[i];
    for (int i = tid; i < 64 * C_ / 4; i += NT) {
        int r = i / 24, c4 = i % 24;
        *(float4*)(os + r * 100 + c4 * 4) =
            *(const float4*)(g_o + ((size_t)(row0 + r)) * C_ + c4 * 4);
    }
    __syncthreads();

    int m = tid >> 2;
    int j0 = (tid & 3) * 24;
    float acc[24];
    #pragma unroll
    for (int u = 0; u < 24; u++) acc[u] = bp[j0 + u];
    #pragma unroll 4
    for (int c = 0; c < C_; c++) {
        float a = os[m * 100 + c];
        const float* wr = Ws + c * C_ + j0;
        #pragma unroll
        for (int u = 0; u < 24; u += 4) {
            float4 wv4 = *(const float4*)(wr + u);
            acc[u + 0] += a * wv4.x; acc[u + 1] += a * wv4.y;
            acc[u + 2] += a * wv4.z; acc[u + 3] += a * wv4.w;
        }
    }
    size_t off = ((size_t)(row0 + m)) * C_ + j0;
    const float* xr = x + off;
    float* outr = out + off;
    #pragma unroll
    for (int u = 0; u < 24; u += 4) {
        float4 xv = *(const float4*)(xr + u);
        *(float4*)(outr + u) = make_float4(acc[u] + xv.x, acc[u + 1] + xv.y,
                                           acc[u + 2] + xv.z, acc[u + 3] + xv.w);
    }
}

// ---------------- launch ----------------
extern "C" void kernel_launch(void* const* d_in, const int* in_sizes, int n_in,
                              void* d_out, int out_size) {
    const float* x     = (const float*)d_in[0];
    const float* gamma = (const float*)d_in[1];
    const float* beta  = (const float*)d_in[2];
    const float* Wq    = (const float*)d_in[3];
    const float* bq    = (const float*)d_in[4];
    const float* Wk    = (const float*)d_in[5];
    const float* bk    = (const float*)d_in[6];
    const float* Wv    = (const float*)d_in[7];
    const float* bv    = (const float*)d_in[8];
    const float* Wp    = (const float*)d_in[9];
    const float* bp    = (const float*)d_in[10];
    float* out = (float*)d_out;

    const int SMEM_GEMM = (C_ * C_ + 64 * 100) * 4;

    cudaFuncSetAttribute(qkv_kernel,  cudaFuncAttributeMaxDynamicSharedMemorySize, SMEM_GEMM);
    cudaFuncSetAttribute(proj_kernel, cudaFuncAttributeMaxDynamicSharedMemorySize, SMEM_GEMM);
    cudaFuncSetAttribute(attn_kernel, cudaFuncAttributeMaxDynamicSharedMemorySize, ATTN_SMEM_BYTES);

    gn_kernel<<<B_ * GROUPS_, NT>>>(x, gamma, beta);
    qkv_kernel<<<dim3(B_ * N_ / 64, 3), NT, SMEM_GEMM>>>(Wq, bq, Wk, bk, Wv, bv);
    attn_kernel<<<dim3(N_ / BM, B_), NT, ATTN_SMEM_BYTES>>>();
    proj_kernel<<<B_ * N_ / 64, NT, SMEM_GEMM>>>(x, Wp, bp, out);
}

// round 5
// speedup vs baseline: 10.2888x; 1.3726x over previous
#include <cuda_runtime.h>
#include <cuda_fp16.h>
#include <cstdint>

#define B_ 2
#define H_ 96
#define W_ 96
#define C_ 96
#define N_ (H_ * W_)          // 9216
#define GROUPS_ 32
#define HPG_ (H_ / GROUPS_)   // 3
#define NT 256
#define BM 128
#define BN 64
#define KT_ (N_ / BN)         // 144 key tiles

// ---------------- scratch (device globals) ----------------
__device__ __half g_qh[B_ * N_ * C_];   // q pre-scaled by 96^-0.5 * log2(e)
__device__ __half g_kh[B_ * N_ * C_];
__device__ __half g_vh[B_ * N_ * C_];
__device__ __half g_oh[B_ * N_ * C_];   // attention output (normalized), fp16
__device__ __align__(16) __half g_W16[4 * 96 * 104];  // Wq,Wk,Wv,Wp fp16, row pitch 104
__device__ float  g_bias[4][C_];
__device__ float  g_a[B_ * H_];          // per-h scale  (gamma*rstd)
__device__ float  g_b[B_ * H_];          // per-h shift  (beta - mean*scale)

// ---------------- helpers ----------------
__device__ __forceinline__ uint32_t smem_u32(const void* p) {
    uint32_t a;
    asm("{ .reg .u64 t; cvta.to.shared.u64 t, %1; cvt.u32.u64 %0, t; }" : "=r"(a) : "l"(p));
    return a;
}
__device__ __forceinline__ void mma_f16(float* d, const uint32_t* a, uint32_t b0, uint32_t b1) {
    asm volatile("mma.sync.aligned.m16n8k16.row.col.f32.f16.f16.f32 "
        "{%0,%1,%2,%3}, {%4,%5,%6,%7}, {%8,%9}, {%0,%1,%2,%3};"
        : "+f"(d[0]), "+f"(d[1]), "+f"(d[2]), "+f"(d[3])
        : "r"(a[0]), "r"(a[1]), "r"(a[2]), "r"(a[3]), "r"(b0), "r"(b1));
}
__device__ __forceinline__ void ldsm4(uint32_t& r0, uint32_t& r1, uint32_t& r2, uint32_t& r3, uint32_t a) {
    asm volatile("ldmatrix.sync.aligned.m8n8.x4.shared.b16 {%0,%1,%2,%3}, [%4];"
        : "=r"(r0), "=r"(r1), "=r"(r2), "=r"(r3) : "r"(a));
}
__device__ __forceinline__ void ldsm4t(uint32_t& r0, uint32_t& r1, uint32_t& r2, uint32_t& r3, uint32_t a) {
    asm volatile("ldmatrix.sync.aligned.m8n8.x4.trans.shared.b16 {%0,%1,%2,%3}, [%4];"
        : "=r"(r0), "=r"(r1), "=r"(r2), "=r"(r3) : "r"(a));
}
__device__ __forceinline__ void ldsm2t(uint32_t& r0, uint32_t& r1, uint32_t a) {
    asm volatile("ldmatrix.sync.aligned.m8n8.x2.trans.shared.b16 {%0,%1}, [%2];"
        : "=r"(r0), "=r"(r1) : "r"(a));
}
__device__ __forceinline__ uint32_t h2pack(float lo, float hi) {
    __half2 h = __floats2half2_rn(lo, hi);
    return *(uint32_t*)&h;
}
__device__ __forceinline__ uint32_t ex2_h2(float lo, float hi) {
    __half2 h = __floats2half2_rn(lo, hi);
    uint32_t u = *(uint32_t*)&h, d;
    asm("ex2.approx.f16x2 %0, %1;" : "=r"(d) : "r"(u));
    return d;
}
#define CP_ASYNC16(d, s) asm volatile("cp.async.cg.shared.global [%0], [%1], 16;" :: "r"(d), "l"(s) : "memory")
#define CP_COMMIT()      asm volatile("cp.async.commit_group;" ::: "memory")
#define CP_WAIT0()       asm volatile("cp.async.wait_group 0;" ::: "memory")

// attn smem byte offsets: rows padded to 104 halves (208B) for conflict-free ldmatrix
#define ROWB 208
#define KB0 0
#define KB1 (KB0 + BN * ROWB)
#define VB0 (KB1 + BN * ROWB)
#define VB1 (VB0 + BN * ROWB)
#define ATTN_SMEM_BYTES (VB1 + BN * ROWB)   // 53248
#define WSMEM_BYTES (96 * ROWB)             // 19968 per weight
#define QKV_SMEM_BYTES (3 * WSMEM_BYTES)    // 59904

// ---------------- GroupNorm stats -> per-h (scale, shift) ----------------
__global__ __launch_bounds__(NT) void gn_stats_kernel(const float* __restrict__ x,
                                                      const float* __restrict__ gamma,
                                                      const float* __restrict__ beta) {
    int bg = blockIdx.x;
    int b = bg / GROUPS_, g = bg % GROUPS_;
    const int LEN = HPG_ * W_ * C_;
    const int NV = LEN / 4;
    size_t base = ((size_t)b * H_ + (size_t)g * HPG_) * (W_ * C_);
    const float4* xv = (const float4*)(x + base);

    float s = 0.f, ss = 0.f;
    for (int i = threadIdx.x; i < NV; i += NT) {
        float4 t = xv[i];
        s  += t.x + t.y + t.z + t.w;
        ss += t.x * t.x + t.y * t.y + t.z * t.z + t.w * t.w;
    }
    #pragma unroll
    for (int o = 16; o; o >>= 1) {
        s  += __shfl_xor_sync(0xffffffffu, s,  o);
        ss += __shfl_xor_sync(0xffffffffu, ss, o);
    }
    __shared__ float red[18];
    int w = threadIdx.x >> 5, l = threadIdx.x & 31;
    if (l == 0) { red[w] = s; red[w + 8] = ss; }
    __syncthreads();
    if (threadIdx.x < 3) {
        float S = 0.f, SS = 0.f;
        #pragma unroll
        for (int i = 0; i < 8; i++) { S += red[i]; SS += red[i + 8]; }
        float mean = S / LEN;
        float var = SS / LEN - mean * mean;
        float rstd = rsqrtf(var + 1e-5f);
        int h = g * HPG_ + threadIdx.x;
        float a = gamma[h] * rstd;
        g_a[b * H_ + h] = a;
        g_b[b * H_ + h] = beta[h] - mean * a;
    }
}

// ---------------- weight prep: fp32 -> fp16 padded rows; bake q scale ----------------
__global__ __launch_bounds__(NT) void w16_prep_kernel(const float* __restrict__ Wq, const float* __restrict__ bq,
                                                      const float* __restrict__ Wk, const float* __restrict__ bk,
                                                      const float* __restrict__ Wv, const float* __restrict__ bv,
                                                      const float* __restrict__ Wp, const float* __restrict__ bp) {
    int wsel = blockIdx.x;
    const float* Wsrc = (wsel == 0) ? Wq : (wsel == 1) ? Wk : (wsel == 2) ? Wv : Wp;
    const float* bsrc = (wsel == 0) ? bq : (wsel == 1) ? bk : (wsel == 2) ? bv : bp;
    const float qs = 0.10206207261596575f * 1.4426950408889634f;
    float sc = (wsel == 0) ? qs : 1.0f;
    for (int i = threadIdx.x; i < C_ * C_; i += NT) {
        int r = i / C_, c = i % C_;
        g_W16[wsel * (96 * 104) + r * 104 + c] = __float2half(Wsrc[i] * sc);
    }
    if (threadIdx.x < C_)
        g_bias[wsel][threadIdx.x] = bsrc[threadIdx.x] * sc;
}

// ---------------- fused GroupNorm + QKV projection via mma ----------------
// grid 144, 256 threads (8 warps x 16 rows). A-frags built from x (normalized
// on the fly, fp16); W tiles (3x) in smem fp16; fp32 accumulate; fp16 out.
__global__ __launch_bounds__(NT) void qkv_mma_kernel(const float* __restrict__ x) {
    extern __shared__ char sm[];
    uint32_t sb = smem_u32(sm);
    int tid = threadIdx.x;
    int w = tid >> 5, l = tid & 31;
    int g = l >> 2, tg = l & 3;

    int row0 = blockIdx.x * BM;
    int b = row0 / N_;
    int mrow = row0 + w * 16;
    int r0 = mrow + g, r1 = mrow + 8 + g;

    // W (3x 96x104h) into smem
    const char* wsrc = (const char*)g_W16;
    for (int i = tid; i < QKV_SMEM_BYTES / 16; i += NT)
        CP_ASYNC16(sb + i * 16, wsrc + i * 16);
    CP_COMMIT();

    // normalize + build A frags
    int h0 = (r0 % N_) / W_, h1 = (r1 % N_) / W_;
    float a0 = g_a[b * H_ + h0], s0 = g_b[b * H_ + h0];
    float a1 = g_a[b * H_ + h1], s1 = g_b[b * H_ + h1];
    const float* x0 = x + (size_t)r0 * C_;
    const float* x1 = x + (size_t)r1 * C_;
    uint32_t af[6][4];
    #pragma unroll
    for (int ks = 0; ks < 6; ks++) {
        float2 v;
        v = *(const float2*)(x0 + ks * 16 + 2 * tg);
        af[ks][0] = h2pack(v.x * a0 + s0, v.y * a0 + s0);
        v = *(const float2*)(x1 + ks * 16 + 2 * tg);
        af[ks][1] = h2pack(v.x * a1 + s1, v.y * a1 + s1);
        v = *(const float2*)(x0 + ks * 16 + 2 * tg + 8);
        af[ks][2] = h2pack(v.x * a0 + s0, v.y * a0 + s0);
        v = *(const float2*)(x1 + ks * 16 + 2 * tg + 8);
        af[ks][3] = h2pack(v.x * a1 + s1, v.y * a1 + s1);
    }

    CP_WAIT0();
    __syncthreads();

    uint32_t vlane = (uint32_t)(((l & 7) + 8 * ((l >> 3) & 1)) * ROWB + 8 * (l >> 4) * 2);

    #pragma unroll
    for (int wi = 0; wi < 3; wi++) {
        float acc[12][4];
        #pragma unroll
        for (int nt = 0; nt < 12; nt++) {
            float2 bi = *(const float2*)(&g_bias[wi][nt * 8 + 2 * tg]);
            acc[nt][0] = bi.x; acc[nt][1] = bi.y;
            acc[nt][2] = bi.x; acc[nt][3] = bi.y;
        }
        uint32_t Wb = sb + wi * WSMEM_BYTES;
        #pragma unroll
        for (int ks = 0; ks < 6; ks++) {
            #pragma unroll
            for (int np = 0; np < 6; np++) {
                uint32_t b0, b1, b2, b3;
                ldsm4t(b0, b1, b2, b3, Wb + (uint32_t)(ks * 16 * ROWB + np * 32) + vlane);
                mma_f16(acc[2 * np],     af[ks], b0, b1);
                mma_f16(acc[2 * np + 1], af[ks], b2, b3);
            }
        }
        __half* outp = (wi == 0) ? g_qh : (wi == 1) ? g_kh : g_vh;
        #pragma unroll
        for (int nt = 0; nt < 12; nt++) {
            *(uint32_t*)(outp + (size_t)r0 * C_ + nt * 8 + 2 * tg) = h2pack(acc[nt][0], acc[nt][1]);
            *(uint32_t*)(outp + (size_t)r1 * C_ + nt * 8 + 2 * tg) = h2pack(acc[nt][2], acc[nt][3]);
        }
    }
}

// ---------------- flash attention, fp16 mma + f16x2 exp + mma row-sums ----------------
__global__ __launch_bounds__(NT, 1) void attn_kernel() {
    extern __shared__ char smc[];
    uint32_t sb = smem_u32(smc);

    int tid = threadIdx.x;
    int w = tid >> 5, l = tid & 31;
    int g = l >> 2, tg = l & 3;
    int b = blockIdx.y, qb = blockIdx.x;

    // Q fragments in registers
    int mrow = qb * BM + w * 16;
    const __half* qg = g_qh + ((size_t)b * N_ + mrow) * C_;
    uint32_t qf[6][4];
    #pragma unroll
    for (int ks = 0; ks < 6; ks++) {
        qf[ks][0] = *(const uint32_t*)(qg + (size_t)g       * C_ + ks * 16 + 2 * tg);
        qf[ks][1] = *(const uint32_t*)(qg + (size_t)(g + 8) * C_ + ks * 16 + 2 * tg);
        qf[ks][2] = *(const uint32_t*)(qg + (size_t)g       * C_ + ks * 16 + 2 * tg + 8);
        qf[ks][3] = *(const uint32_t*)(qg + (size_t)(g + 8) * C_ + ks * 16 + 2 * tg + 8);
    }

    float o[12][4], o_l[4];
    #pragma unroll
    for (int nt = 0; nt < 12; nt++)
        #pragma unroll
        for (int j = 0; j < 4; j++) o[nt][j] = 0.f;
    o_l[0] = o_l[1] = o_l[2] = o_l[3] = 0.f;
    float m0 = -3.0e38f, m1 = -3.0e38f;

    uint32_t klane = (uint32_t)(((l & 7) + 8 * ((l >> 4) & 1)) * ROWB + 8 * ((l >> 3) & 1) * 2);
    uint32_t vlane = (uint32_t)(((l & 7) + 8 * ((l >> 3) & 1)) * ROWB + 8 * (l >> 4) * 2);
    uint32_t oneslane = (uint32_t)(((l & 7) + 8 * ((l >> 3) & 1)) * ROWB + 192);

    const __half* kbase = g_kh + (size_t)b * N_ * C_;
    const __half* vbase = g_vh + (size_t)b * N_ * C_;

    auto load_kv = [&](int kt, int buf) {
        const __half* kg = kbase + (size_t)kt * BN * C_;
        const __half* vg = vbase + (size_t)kt * BN * C_;
        uint32_t kb = sb + (buf ? KB1 : KB0);
        uint32_t vb = sb + (buf ? VB1 : VB0);
        #pragma unroll
        for (int i = 0; i < 3; i++) {
            int c = tid + i * NT;            // 0..767
            int row = c / 12, q = c % 12;
            uint32_t so = (uint32_t)(row * ROWB + q * 16);
            CP_ASYNC16(kb + so, kg + row * C_ + q * 8);
            CP_ASYNC16(vb + so, vg + row * C_ + q * 8);
        }
        // ones column at V col 96 (bytes 192..193 of each row)
        if (tid < BN)
            *(__half*)(smc + (buf ? VB1 : VB0) + tid * ROWB + 192) = __float2half(1.0f);
    };

    load_kv(0, 0);
    CP_COMMIT();

    for (int t = 0; t < KT_; t++) {
        int buf = t & 1;
        uint32_t Kb = sb + (buf ? KB1 : KB0);
        uint32_t Vb = sb + (buf ? VB1 : VB0);

        CP_WAIT0();
        __syncthreads();
        if (t + 1 < KT_) { load_kv(t + 1, buf ^ 1); CP_COMMIT(); }

        // ---- S = Q K^T ----
        float s[8][4];
        #pragma unroll
        for (int nt = 0; nt < 8; nt++)
            #pragma unroll
            for (int j = 0; j < 4; j++) s[nt][j] = 0.f;

        #pragma unroll
        for (int ks = 0; ks < 6; ks++) {
            #pragma unroll
            for (int np = 0; np < 4; np++) {
                uint32_t b0, b1, b2, b3;
                ldsm4(b0, b1, b2, b3, Kb + (uint32_t)(np * 16 * ROWB + ks * 32) + klane);
                mma_f16(s[2 * np],     qf[ks], b0, b1);
                mma_f16(s[2 * np + 1], qf[ks], b2, b3);
            }
        }

        // ---- online softmax: max reduce, then packed f16x2 exp2 ----
        float rm0 = -3.0e38f, rm1 = -3.0e38f;
        #pragma unroll
        for (int nt = 0; nt < 8; nt++) {
            rm0 = fmaxf(rm0, fmaxf(s[nt][0], s[nt][1]));
            rm1 = fmaxf(rm1, fmaxf(s[nt][2], s[nt][3]));
        }
        rm0 = fmaxf(rm0, __shfl_xor_sync(0xffffffffu, rm0, 1));
        rm0 = fmaxf(rm0, __shfl_xor_sync(0xffffffffu, rm0, 2));
        rm1 = fmaxf(rm1, __shfl_xor_sync(0xffffffffu, rm1, 1));
        rm1 = fmaxf(rm1, __shfl_xor_sync(0xffffffffu, rm1, 2));

        float mn0 = fmaxf(m0, rm0), mn1 = fmaxf(m1, rm1);
        float a0 = exp2f(m0 - mn0), a1 = exp2f(m1 - mn1);
        m0 = mn0; m1 = mn1;

        uint32_t pu[8][2];
        #pragma unroll
        for (int nt = 0; nt < 8; nt++) {
            pu[nt][0] = ex2_h2(s[nt][0] - mn0, s[nt][1] - mn0);
            pu[nt][1] = ex2_h2(s[nt][2] - mn1, s[nt][3] - mn1);
        }

        // rescale O (+ row-sum accumulator)
        #pragma unroll
        for (int nt = 0; nt < 12; nt++) {
            o[nt][0] *= a0; o[nt][1] *= a0;
            o[nt][2] *= a1; o[nt][3] *= a1;
        }
        o_l[0] *= a0; o_l[1] *= a0; o_l[2] *= a1; o_l[3] *= a1;

        // ---- O += P V ; row sums via ones column ----
        #pragma unroll
        for (int ks = 0; ks < 4; ks++) {
            uint32_t pa[4] = { pu[2 * ks][0], pu[2 * ks][1], pu[2 * ks + 1][0], pu[2 * ks + 1][1] };
            #pragma unroll
            for (int np = 0; np < 6; np++) {
                uint32_t b0, b1, b2, b3;
                ldsm4t(b0, b1, b2, b3, Vb + (uint32_t)(ks * 16 * ROWB + np * 32) + vlane);
                mma_f16(o[2 * np],     pa, b0, b1);
                mma_f16(o[2 * np + 1], pa, b2, b3);
            }
            uint32_t c0, c1;
            ldsm2t(c0, c1, Vb + (uint32_t)(ks * 16 * ROWB) + oneslane);
            mma_f16(o_l, pa, c0, c1);
        }
    }

    // ---- epilogue: broadcast row sums, normalize, fp16 store ----
    float l0 = __shfl_sync(0xffffffffu, o_l[0], l & 28);
    float l1 = __shfl_sync(0xffffffffu, o_l[2], l & 28);
    float i0 = 1.0f / l0, i1 = 1.0f / l1;
    __half* og = g_oh + ((size_t)b * N_ + mrow) * C_;
    #pragma unroll
    for (int nt = 0; nt < 12; nt++) {
        *(uint32_t*)(og + (size_t)g       * C_ + nt * 8 + 2 * tg) = h2pack(o[nt][0] * i0, o[nt][1] * i0);
        *(uint32_t*)(og + (size_t)(g + 8) * C_ + nt * 8 + 2 * tg) = h2pack(o[nt][2] * i1, o[nt][3] * i1);
    }
}

// ---------------- final projection + residual via mma ----------------
__global__ __launch_bounds__(NT) void proj_mma_kernel(const float* __restrict__ x,
                                                      float* __restrict__ out) {
    extern __shared__ char sm[];
    uint32_t sb = smem_u32(sm);
    int tid = threadIdx.x;
    int w = tid >> 5, l = tid & 31;
    int g = l >> 2, tg = l & 3;

    int row0 = blockIdx.x * BM;
    int mrow = row0 + w * 16;
    int r0 = mrow + g, r1 = mrow + 8 + g;

    // Wp into smem
    const char* wsrc = (const char*)g_W16 + 3 * WSMEM_BYTES;
    for (int i = tid; i < WSMEM_BYTES / 16; i += NT)
        CP_ASYNC16(sb + i * 16, wsrc + i * 16);
    CP_COMMIT();

    // A frags from attention output (already fp16 pairs)
    const __half* o0 = g_oh + (size_t)r0 * C_;
    const __half* o1 = g_oh + (size_t)r1 * C_;
    uint32_t af[6][4];
    #pragma unroll
    for (int ks = 0; ks < 6; ks++) {
        af[ks][0] = *(const uint32_t*)(o0 + ks * 16 + 2 * tg);
        af[ks][1] = *(const uint32_t*)(o1 + ks * 16 + 2 * tg);
        af[ks][2] = *(const uint32_t*)(o0 + ks * 16 + 2 * tg + 8);
        af[ks][3] = *(const uint32_t*)(o1 + ks * 16 + 2 * tg + 8);
    }

    CP_WAIT0();
    __syncthreads();

    uint32_t vlane = (uint32_t)(((l & 7) + 8 * ((l >> 3) & 1)) * ROWB + 8 * (l >> 4) * 2);

    float acc[12][4];
    #pragma unroll
    for (int nt = 0; nt < 12; nt++) {
        float2 bi = *(const float2*)(&g_bias[3][nt * 8 + 2 * tg]);
        acc[nt][0] = bi.x; acc[nt][1] = bi.y;
        acc[nt][2] = bi.x; acc[nt][3] = bi.y;
    }
    #pragma unroll
    for (int ks = 0; ks < 6; ks++) {
        #pragma unroll
        for (int np = 0; np < 6; np++) {
            uint32_t b0, b1, b2, b3;
            ldsm4t(b0, b1, b2, b3, sb + (uint32_t)(ks * 16 * ROWB + np * 32) + vlane);
            mma_f16(acc[2 * np],     af[ks], b0, b1);
            mma_f16(acc[2 * np + 1], af[ks], b2, b3);
        }
    }

    // residual + store fp32
    const float* x0 = x + (size_t)r0 * C_;
    const float* x1 = x + (size_t)r1 * C_;
    float* y0 = out + (size_t)r0 * C_;
    float* y1 = out + (size_t)r1 * C_;
    #pragma unroll
    for (int nt = 0; nt < 12; nt++) {
        int c = nt * 8 + 2 * tg;
        float2 xv;
        xv = *(const float2*)(x0 + c);
        *(float2*)(y0 + c) = make_float2(acc[nt][0] + xv.x, acc[nt][1] + xv.y);
        xv = *(const float2*)(x1 + c);
        *(float2*)(y1 + c) = make_float2(acc[nt][2] + xv.x, acc[nt][3] + xv.y);
    }
}

// ---------------- launch ----------------
extern "C" void kernel_launch(void* const* d_in, const int* in_sizes, int n_in,
                              void* d_out, int out_size) {
    const float* x     = (const float*)d_in[0];
    const float* gamma = (const float*)d_in[1];
    const float* beta  = (const float*)d_in[2];
    const float* Wq    = (const float*)d_in[3];
    const float* bq    = (const float*)d_in[4];
    const float* Wk    = (const float*)d_in[5];
    const float* bk    = (const float*)d_in[6];
    const float* Wv    = (const float*)d_in[7];
    const float* bv    = (const float*)d_in[8];
    const float* Wp    = (const float*)d_in[9];
    const float* bp    = (const float*)d_in[10];
    float* out = (float*)d_out;

    cudaFuncSetAttribute(qkv_mma_kernel,  cudaFuncAttributeMaxDynamicSharedMemorySize, QKV_SMEM_BYTES);
    cudaFuncSetAttribute(attn_kernel,     cudaFuncAttributeMaxDynamicSharedMemorySize, ATTN_SMEM_BYTES);
    cudaFuncSetAttribute(proj_mma_kernel, cudaFuncAttributeMaxDynamicSharedMemorySize, WSMEM_BYTES);

    gn_stats_kernel<<<B_ * GROUPS_, NT>>>(x, gamma, beta);
    w16_prep_kernel<<<4, NT>>>(Wq, bq, Wk, bk, Wv, bv, Wp, bp);
    qkv_mma_kernel<<<B_ * N_ / BM, NT, QKV_SMEM_BYTES>>>(x);
    attn_kernel<<<dim3(N_ / BM, B_), NT, ATTN_SMEM_BYTES>>>();
    proj_mma_kernel<<<B_ * N_ / BM, NT, WSMEM_BYTES>>>(x, out);
}